// round 8
// baseline (speedup 1.0000x reference)
#include <cuda_runtime.h>

// Math collapse: K and V rows are identical across the sequence dim (age is
// broadcast before the K/V projections), so every score row is constant,
// softmax weights are exactly 1/N, and attended[b,n,:] == age[b]@Wv + bv.
// Output = pixel + broadcast(age @ Wv + bv) over n.
//
// Fused kernel, power-of-two tiling: blocks own a (256-row x 128-col) tile.
// Preamble computes the 128-col slice of vb (split-K x4, all 512 threads).
// Stream loop: per-thread column is FIXED -> vb value hoisted to a register;
// body is LDG.128 + 4 FADD + STG.128 with pointer-increment addressing.

#define B_DIM 8
#define N_DIM 2048
#define D_DIM 768
#define A_DIM 128

#define DCH   6                        // d-chunks of 128 floats
#define NCH   8                        // n-chunks of 256 rows
#define DSUB  128
#define DSUB4 32                       // float4 per d-chunk
#define NROWS 256
#define TPB   512
#define KSPL  4
#define RSTRIDE4 (D_DIM / 4)           // 192 float4 per full row

__global__ __launch_bounds__(TPB)
void fused_cross_attn_kernel(const float* __restrict__ pixel,
                             const float* __restrict__ age,
                             const float* __restrict__ Wv,
                             const float* __restrict__ bv,
                             float* __restrict__ out) {
    __shared__ __align__(16) float s_age[A_DIM];
    __shared__ __align__(16) float s_part[KSPL * DSUB];
    __shared__ __align__(16) float s_vb[DSUB];

    const int tid = threadIdx.x;
    const int dch = blockIdx.x;        // 0..5
    const int nch = blockIdx.y;        // 0..7
    const int b   = blockIdx.z;        // 0..7
    const int d0  = dch * DSUB;

    if (tid < A_DIM) s_age[tid] = age[b * A_DIM + tid];
    __syncthreads();

    // ---- preamble: all 512 threads, split-K x4 over the 128-col slice
    {
        const int dl = tid & (DSUB - 1);           // 0..127, coalesced Wv
        const int k  = tid >> 7;                   // 0..3
        const int dg = d0 + dl;
        float acc = 0.f;
#pragma unroll
        for (int i = 0; i < A_DIM / KSPL; i++) {
            const int a = k * (A_DIM / KSPL) + i;
            acc = fmaf(s_age[a], Wv[a * D_DIM + dg], acc);
        }
        s_part[k * DSUB + dl] = acc;
    }
    __syncthreads();
    if (tid < DSUB) {
        s_vb[tid] = bv[d0 + tid] + ((s_part[tid] + s_part[DSUB + tid]) +
                    (s_part[2 * DSUB + tid] + s_part[3 * DSUB + tid]));
    }
    __syncthreads();

    // ---- stream: out[b, n0:n0+256, d0:d0+128] = pixel + vb
    const int c  = tid & (DSUB4 - 1);              // fixed column (float4)
    const int r0 = tid >> 5;                       // 0..15
    const float4 v = reinterpret_cast<const float4*>(s_vb)[c];

    const int n0 = nch * NROWS;
    const int base4 = (b * N_DIM + n0 + r0) * RSTRIDE4 + dch * DSUB4 + c;
    const float4* __restrict__ p4 = reinterpret_cast<const float4*>(pixel) + base4;
    float4* __restrict__       o4 = reinterpret_cast<float4*>(out) + base4;
    const int step = (TPB / DSUB4) * RSTRIDE4;     // 16 rows * 192

#pragma unroll
    for (int it = 0; it < NROWS / (TPB / DSUB4); it++) {   // 16 iters
        float4 p = __ldcs(p4);
        p.x += v.x; p.y += v.y; p.z += v.z; p.w += v.w;
        __stcs(o4, p);
        p4 += step; o4 += step;
    }
}

extern "C" void kernel_launch(void* const* d_in, const int* in_sizes, int n_in,
                              void* d_out, int out_size) {
    // metadata order: pixel_features, age_features, Wq, bq, Wk, bk, Wv, bv
    const float* pixel = (const float*)d_in[0];
    const float* age   = (const float*)d_in[1];
    const float* Wv    = (const float*)d_in[6];
    const float* bv    = (const float*)d_in[7];
    float* out = (float*)d_out;

    dim3 grid(DCH, NCH, B_DIM);
    fused_cross_attn_kernel<<<grid, TPB>>>(pixel, age, Wv, bv, out);
}

// round 10
// speedup vs baseline: 1.1194x; 1.1194x over previous
#include <cuda_runtime.h>

// Math collapse: K and V rows are identical across the sequence dim (age is
// broadcast before the K/V projections), so every score row is constant,
// softmax weights are exactly 1/N, and attended[b,n,:] == age[b]@Wv + bv.
// Output = pixel + broadcast(age @ Wv + bv) over n.
//
// Fused kernel. Blocks own a (256-row x 128-col) tile; preamble computes the
// 128-col slice of vb (split-K x4, all 512 threads). Stream loop: fixed
// per-thread column (vb hoisted to a register), and 8 LDG.128 batched into a
// register array per iteration to force MLP_p1~8 (R8 post-mortem: ptxas
// register-minimized the tight loop to MLP~2 and HBM dropped 14%).

#define B_DIM 8
#define N_DIM 2048
#define D_DIM 768
#define A_DIM 128

#define DCH   6                        // d-chunks of 128 floats
#define NCH   8                        // n-chunks of 256 rows
#define DSUB  128
#define DSUB4 32                       // float4 per d-chunk
#define NROWS 256
#define TPB   512
#define KSPL  4
#define RSTRIDE4 (D_DIM / 4)           // 192 float4 per full row
#define BATCH 8                        // loads in flight per thread

__global__ __launch_bounds__(TPB, 2)   // cap 64 regs: room for 8 float4 in flight
void fused_cross_attn_kernel(const float* __restrict__ pixel,
                             const float* __restrict__ age,
                             const float* __restrict__ Wv,
                             const float* __restrict__ bv,
                             float* __restrict__ out) {
    __shared__ __align__(16) float s_age[A_DIM];
    __shared__ __align__(16) float s_part[KSPL * DSUB];
    __shared__ __align__(16) float s_vb[DSUB];

    const int tid = threadIdx.x;
    const int dch = blockIdx.x;        // 0..5
    const int nch = blockIdx.y;        // 0..7
    const int b   = blockIdx.z;        // 0..7
    const int d0  = dch * DSUB;

    if (tid < A_DIM) s_age[tid] = age[b * A_DIM + tid];
    __syncthreads();

    // ---- preamble: all 512 threads, split-K x4 over the 128-col slice
    {
        const int dl = tid & (DSUB - 1);           // 0..127, coalesced Wv
        const int k  = tid >> 7;                   // 0..3
        const int dg = d0 + dl;
        float acc = 0.f;
#pragma unroll
        for (int i = 0; i < A_DIM / KSPL; i++) {
            const int a = k * (A_DIM / KSPL) + i;
            acc = fmaf(s_age[a], Wv[a * D_DIM + dg], acc);
        }
        s_part[k * DSUB + dl] = acc;
    }
    __syncthreads();
    if (tid < DSUB) {
        s_vb[tid] = bv[d0 + tid] + ((s_part[tid] + s_part[DSUB + tid]) +
                    (s_part[2 * DSUB + tid] + s_part[3 * DSUB + tid]));
    }
    __syncthreads();

    // ---- stream: out[b, n0:n0+256, d0:d0+128] = pixel + vb
    const int c  = tid & (DSUB4 - 1);              // fixed column (float4)
    const int r0 = tid >> 5;                       // 0..15
    const float4 v = reinterpret_cast<const float4*>(s_vb)[c];

    const int n0 = nch * NROWS;
    const int base4 = (b * N_DIM + n0 + r0) * RSTRIDE4 + dch * DSUB4 + c;
    const float4* __restrict__ p4 = reinterpret_cast<const float4*>(pixel) + base4;
    float4* __restrict__       o4 = reinterpret_cast<float4*>(out) + base4;
    const int step = (TPB / DSUB4) * RSTRIDE4;     // 16 rows * 192

    // 16 rows per thread = 2 iterations of 8 batched load/store pairs
#pragma unroll 1
    for (int it = 0; it < NROWS / (TPB / DSUB4) / BATCH; it++) {   // 2 iters
        float4 r[BATCH];
#pragma unroll
        for (int j = 0; j < BATCH; j++) r[j] = p4[j * step];       // 8 LDG batched
#pragma unroll
        for (int j = 0; j < BATCH; j++) {
            r[j].x += v.x; r[j].y += v.y; r[j].z += v.z; r[j].w += v.w;
            o4[j * step] = r[j];
        }
        p4 += BATCH * step; o4 += BATCH * step;
    }
}

extern "C" void kernel_launch(void* const* d_in, const int* in_sizes, int n_in,
                              void* d_out, int out_size) {
    // metadata order: pixel_features, age_features, Wq, bq, Wk, bk, Wv, bv
    const float* pixel = (const float*)d_in[0];
    const float* age   = (const float*)d_in[1];
    const float* Wv    = (const float*)d_in[6];
    const float* bv    = (const float*)d_in[7];
    float* out = (float*)d_out;

    dim3 grid(DCH, NCH, B_DIM);
    fused_cross_attn_kernel<<<grid, TPB>>>(pixel, age, Wv, bv, out);
}

// round 12
// speedup vs baseline: 1.1215x; 1.0019x over previous
#include <cuda_runtime.h>

// Math collapse: K and V rows are identical across the sequence dim (age is
// broadcast before the K/V projections), so every score row is constant,
// softmax weights are exactly 1/N, and attended[b,n,:] == age[b]@Wv + bv.
// Output = pixel + broadcast(age @ Wv + bv) over n.
//
// Fused kernel, SINGLE-WAVE grid (R10 post-mortem: 384 blocks at 2-CTA/SM
// capacity 296 left an 88-block tail wave at 30% SM coverage; 256-thread
// blocks raise capacity to ~592 so all 384 blocks are co-resident).
// Stream loop: fixed per-thread column (vb in a register), 8 LDG.128 batched
// per iteration for MLP~8.

#define B_DIM 8
#define N_DIM 2048
#define D_DIM 768
#define A_DIM 128

#define DCH   6                        // d-chunks of 128 floats
#define NCH   8                        // n-chunks of 256 rows
#define DSUB  128
#define DSUB4 32                       // float4 per d-chunk
#define NROWS 256
#define TPB   256
#define KSPL  2
#define RSTRIDE4 (D_DIM / 4)           // 192 float4 per full row
#define BATCH 8                        // loads in flight per thread
#define RPT   (NROWS / (TPB / DSUB4))  // 32 rows per thread

__global__ __launch_bounds__(TPB, 4)   // cap 64 regs -> 4 CTA/SM
void fused_cross_attn_kernel(const float* __restrict__ pixel,
                             const float* __restrict__ age,
                             const float* __restrict__ Wv,
                             const float* __restrict__ bv,
                             float* __restrict__ out) {
    __shared__ __align__(16) float s_age[A_DIM];
    __shared__ __align__(16) float s_part[KSPL * DSUB];
    __shared__ __align__(16) float s_vb[DSUB];

    const int tid = threadIdx.x;
    const int dch = blockIdx.x;        // 0..5
    const int nch = blockIdx.y;        // 0..7
    const int b   = blockIdx.z;        // 0..7
    const int d0  = dch * DSUB;

    if (tid < A_DIM) s_age[tid] = age[b * A_DIM + tid];
    __syncthreads();

    // ---- preamble: 256 threads, split-K x2 over the 128-col slice
    {
        const int dl = tid & (DSUB - 1);           // 0..127, coalesced Wv
        const int k  = tid >> 7;                   // 0..1
        const int dg = d0 + dl;
        float acc = 0.f;
#pragma unroll
        for (int i = 0; i < A_DIM / KSPL; i++) {
            const int a = k * (A_DIM / KSPL) + i;
            acc = fmaf(s_age[a], Wv[a * D_DIM + dg], acc);
        }
        s_part[k * DSUB + dl] = acc;
    }
    __syncthreads();
    if (tid < DSUB) {
        s_vb[tid] = bv[d0 + tid] + (s_part[tid] + s_part[DSUB + tid]);
    }
    __syncthreads();

    // ---- stream: out[b, n0:n0+256, d0:d0+128] = pixel + vb
    const int c  = tid & (DSUB4 - 1);              // fixed column (float4)
    const int r0 = tid >> 5;                       // 0..7
    const float4 v = reinterpret_cast<const float4*>(s_vb)[c];

    const int n0 = nch * NROWS;
    const int base4 = (b * N_DIM + n0 + r0) * RSTRIDE4 + dch * DSUB4 + c;
    const float4* __restrict__ p4 = reinterpret_cast<const float4*>(pixel) + base4;
    float4* __restrict__       o4 = reinterpret_cast<float4*>(out) + base4;
    const int step = (TPB / DSUB4) * RSTRIDE4;     // 8 rows * 192

    // 32 rows per thread = 4 iterations of 8 batched load/store pairs
#pragma unroll 1
    for (int it = 0; it < RPT / BATCH; it++) {     // 4 iters
        float4 r[BATCH];
#pragma unroll
        for (int j = 0; j < BATCH; j++) r[j] = p4[j * step];       // 8 LDG batched
#pragma unroll
        for (int j = 0; j < BATCH; j++) {
            r[j].x += v.x; r[j].y += v.y; r[j].z += v.z; r[j].w += v.w;
            o4[j * step] = r[j];
        }
        p4 += BATCH * step; o4 += BATCH * step;
    }
}

extern "C" void kernel_launch(void* const* d_in, const int* in_sizes, int n_in,
                              void* d_out, int out_size) {
    // metadata order: pixel_features, age_features, Wq, bq, Wk, bk, Wv, bv
    const float* pixel = (const float*)d_in[0];
    const float* age   = (const float*)d_in[1];
    const float* Wv    = (const float*)d_in[6];
    const float* bv    = (const float*)d_in[7];
    float* out = (float*)d_out;

    dim3 grid(DCH, NCH, B_DIM);
    fused_cross_attn_kernel<<<grid, TPB>>>(pixel, age, Wv, bv, out);
}